// round 14
// baseline (speedup 1.0000x reference)
#include <cuda_runtime.h>
#include <cuda_fp16.h>
#include <math_constants.h>
#include <stdint.h>

#define NROWS  32768
#define DIM    256
#define KCODES 8192

#define BM 128
#define BN 128
#define NTILES (KCODES / BN)   // 64
#define WINDOW 0.75f           // scaled-dot domain (dot * 4096)

#define ASTRIDE 528            // 256 f16 = 512B + 16B pad (conflict-free ldmatrix)
#define A_OFF 0
#define A_SZ  (BM * ASTRIDE)               // 67584
#define B_OFF A_SZ
#define B_SZ  (BN * ASTRIDE)               // 67584
#define SMEM_TOTAL (A_SZ + 2 * B_SZ)       // 202752

// post-loop areas reuse the dead B-buffer region
#define CAND_OFF     B_OFF                 // 128 rows * 8 writers * 3 ents * 8B = 24576
#define OVF_LIST_OFF (B_OFF + 24576)
#define OVF_CNT_OFF  (OVF_LIST_OFF + 128 * 4)
#define SEL_OFF      (OVF_CNT_OFF + 16)    // int[128] final indices

__device__ float  g_a[NROWS];
__device__ float  g_c[KCODES];
__device__ __align__(16) __half g_xh[NROWS * DIM];
__device__ __align__(16) __half g_wh[KCODES * DIM];   // W * 4096

// ---------------- asm helpers (sm_103-base-target legal) ----------------
__device__ __forceinline__ uint32_t smem_u32(const void* p) {
    uint32_t a;
    asm("{ .reg .u64 t; cvta.to.shared.u64 t, %1; cvt.u32.u64 %0, t; }" : "=r"(a) : "l"(p));
    return a;
}
__device__ __forceinline__ void cp16(uint32_t s, const void* g) {
    asm volatile("cp.async.cg.shared.global [%0], [%1], 16;" :: "r"(s), "l"(g));
}
#define CP_COMMIT() asm volatile("cp.async.commit_group;" ::: "memory")
#define CP_WAIT0()  asm volatile("cp.async.wait_group 0;" ::: "memory")

__device__ __forceinline__ void ldsm4(uint32_t addr, uint32_t& r0, uint32_t& r1,
                                      uint32_t& r2, uint32_t& r3) {
    asm volatile("ldmatrix.sync.aligned.m8n8.x4.shared.b16 {%0,%1,%2,%3}, [%4];"
                 : "=r"(r0), "=r"(r1), "=r"(r2), "=r"(r3) : "r"(addr));
}
__device__ __forceinline__ void mma16816(float* c, const uint32_t* a, const uint32_t* b) {
    asm volatile(
        "mma.sync.aligned.m16n8k16.row.col.f32.f16.f16.f32 "
        "{%0,%1,%2,%3}, {%4,%5,%6,%7}, {%8,%9}, {%0,%1,%2,%3};"
        : "+f"(c[0]), "+f"(c[1]), "+f"(c[2]), "+f"(c[3])
        : "r"(a[0]), "r"(a[1]), "r"(a[2]), "r"(a[3]), "r"(b[0]), "r"(b[1]));
}

// ---------------- prep kernels (proven) ----------------
__global__ void vq_prep_x(const float* __restrict__ x, float* __restrict__ a,
                          __half* __restrict__ xh) {
    int warp = (blockIdx.x * blockDim.x + threadIdx.x) >> 5;
    int lane = threadIdx.x & 31;
    if (warp >= NROWS) return;
    const float4* r4 = (const float4*)(x + (size_t)warp * DIM);
    float4 v0 = r4[lane * 2 + 0], v1 = r4[lane * 2 + 1];
    float s = 0.f;
    s = fmaf(v0.x, v0.x, s); s = fmaf(v0.y, v0.y, s); s = fmaf(v0.z, v0.z, s); s = fmaf(v0.w, v0.w, s);
    s = fmaf(v1.x, v1.x, s); s = fmaf(v1.y, v1.y, s); s = fmaf(v1.z, v1.z, s); s = fmaf(v1.w, v1.w, s);
    #pragma unroll
    for (int o = 16; o; o >>= 1) s += __shfl_xor_sync(0xffffffffu, s, o);
    if (lane == 0) a[warp] = s;
    __half2 h0 = __floats2half2_rn(v0.x, v0.y), h1 = __floats2half2_rn(v0.z, v0.w);
    __half2 h2 = __floats2half2_rn(v1.x, v1.y), h3 = __floats2half2_rn(v1.z, v1.w);
    uint4 u;
    u.x = *(unsigned*)&h0; u.y = *(unsigned*)&h1; u.z = *(unsigned*)&h2; u.w = *(unsigned*)&h3;
    ((uint4*)(xh + (size_t)warp * DIM))[lane] = u;
}
__global__ void vq_prep_w(const float* __restrict__ w, float* __restrict__ c,
                          __half* __restrict__ wh) {
    int warp = (blockIdx.x * blockDim.x + threadIdx.x) >> 5;
    int lane = threadIdx.x & 31;
    if (warp >= KCODES) return;
    const float4* r4 = (const float4*)(w + (size_t)warp * DIM);
    float4 v0 = r4[lane * 2 + 0], v1 = r4[lane * 2 + 1];
    float s = 0.f;
    s = fmaf(v0.x, v0.x, s); s = fmaf(v0.y, v0.y, s); s = fmaf(v0.z, v0.z, s); s = fmaf(v0.w, v0.w, s);
    s = fmaf(v1.x, v1.x, s); s = fmaf(v1.y, v1.y, s); s = fmaf(v1.z, v1.z, s); s = fmaf(v1.w, v1.w, s);
    #pragma unroll
    for (int o = 16; o; o >>= 1) s += __shfl_xor_sync(0xffffffffu, s, o);
    if (lane == 0) c[warp] = s;
    const float SC = 4096.0f;
    __half2 h0 = __floats2half2_rn(v0.x * SC, v0.y * SC), h1 = __floats2half2_rn(v0.z * SC, v0.w * SC);
    __half2 h2 = __floats2half2_rn(v1.x * SC, v1.y * SC), h3 = __floats2half2_rn(v1.z * SC, v1.w * SC);
    uint4 u;
    u.x = *(unsigned*)&h0; u.y = *(unsigned*)&h1; u.z = *(unsigned*)&h2; u.w = *(unsigned*)&h3;
    ((uint4*)(wh + (size_t)warp * DIM))[lane] = u;
}

// ---------------- screen kernel (HMMA, 4 warps / 1 per SMSP, fused gather) ----------------
__global__ __launch_bounds__(128, 1)
void vq_screen(const float* __restrict__ X, const float* __restrict__ W,
               const __half* __restrict__ Xh, const __half* __restrict__ Wh,
               float* __restrict__ out, float* __restrict__ out_idx) {
    extern __shared__ char smem[];
    const uint32_t sb = smem_u32(smem);
    const int tid = threadIdx.x;
    const int wid = tid >> 5, lane = tid & 31;
    const int warp_m = wid >> 1, warp_n = wid & 1;   // 2x2 warp grid: 64x64 tiles
    const int g = lane >> 2, t = lane & 3;
    const int rBase = blockIdx.x * BM;

    // ---- prologue: A tile + B tile 0 via cp.async (32 cp16 each per thread) ----
    #pragma unroll
    for (int i = 0; i < 32; i++) {
        int idx = tid + i * 128;               // 0..4095
        int row = idx >> 5, c = idx & 31;
        cp16(sb + A_OFF + row * ASTRIDE + c * 16,
             Xh + (size_t)(rBase + row) * DIM + c * 8);
    }
    #pragma unroll
    for (int i = 0; i < 32; i++) {
        int idx = tid + i * 128;
        int row = idx >> 5, c = idx & 31;
        cp16(sb + B_OFF + row * ASTRIDE + c * 16,
             Wh + (size_t)row * DIM + c * 8);
    }
    CP_COMMIT();

    // per-(lane,slot) top-2 + restmax; slot s = mi*2+h (8 slots, 16 codes each)
    float cv1[8], cv2[8], cv3[8];
    int   ck1[8], ck2[8];
    #pragma unroll
    for (int s = 0; s < 8; s++) {
        cv1[s] = cv2[s] = cv3[s] = -CUDART_INF_F;
        ck1[s] = ck2[s] = 0;
    }

    // ldmatrix bases — A mapping identical to proven round-4 kernel
    const uint32_t a_base = sb + A_OFF +
        (uint32_t)(warp_m * 64 + (lane & 15)) * ASTRIDE + (uint32_t)(lane >> 4) * 16;
    const uint32_t b_row_off =
        (uint32_t)(warp_n * 64 + (lane & 7) + (lane >> 4) * 8) * ASTRIDE +
        (uint32_t)((lane >> 3) & 1) * 16;

    for (int nt = 0; nt < NTILES; nt++) {
        CP_WAIT0();
        __syncthreads();
        if (nt + 1 < NTILES) {
            int buf = (nt + 1) & 1;
            #pragma unroll
            for (int i = 0; i < 32; i++) {
                int idx = tid + i * 128;
                int row = idx >> 5, c = idx & 31;
                cp16(sb + B_OFF + buf * B_SZ + row * ASTRIDE + c * 16,
                     Wh + (size_t)((nt + 1) * BN + row) * DIM + c * 8);
            }
            CP_COMMIT();
        }

        // ---- GEMM: 64x64 warp tile over K=256 ----
        float acc[4][8][4];
        #pragma unroll
        for (int mi = 0; mi < 4; mi++)
            #pragma unroll
            for (int ni = 0; ni < 8; ni++)
                #pragma unroll
                for (int c = 0; c < 4; c++) acc[mi][ni][c] = 0.f;

        const uint32_t b_base = sb + B_OFF + (uint32_t)(nt & 1) * B_SZ + b_row_off;
        for (int ks = 0; ks < 16; ks++) {
            uint32_t af[4][4], bf[8][2];
            #pragma unroll
            for (int mi = 0; mi < 4; mi++)
                ldsm4(a_base + (uint32_t)mi * 16 * ASTRIDE + (uint32_t)ks * 32,
                      af[mi][0], af[mi][1], af[mi][2], af[mi][3]);
            #pragma unroll
            for (int nj = 0; nj < 4; nj++)
                ldsm4(b_base + (uint32_t)nj * 16 * ASTRIDE + (uint32_t)ks * 32,
                      bf[nj * 2][0], bf[nj * 2][1], bf[nj * 2 + 1][0], bf[nj * 2 + 1][1]);
            #pragma unroll
            for (int mi = 0; mi < 4; mi++)
                #pragma unroll
                for (int ni = 0; ni < 8; ni++)
                    mma16816(acc[mi][ni], af[mi], bf[ni]);
        }

        // ---- epilogue: per-slot top-2 + restmax over 16 codes ----
        #pragma unroll
        for (int mi = 0; mi < 4; mi++) {
            #pragma unroll
            for (int h = 0; h < 2; h++) {
                const int s = mi * 2 + h;
                float tm = -CUDART_INF_F;
                #pragma unroll
                for (int ni = 0; ni < 8; ni++)
                    tm = fmaxf(tm, fmaxf(acc[mi][ni][2 * h], acc[mi][ni][2 * h + 1]));
                if (tm <= cv2[s]) {
                    cv3[s] = fmaxf(cv3[s], tm);
                } else {
                    #pragma unroll
                    for (int ni = 0; ni < 8; ni++) {
                        #pragma unroll
                        for (int c = 0; c < 2; c++) {
                            float v = acc[mi][ni][2 * h + c];
                            int kk = nt * BN + warp_n * 64 + ni * 8 + 2 * t + c;
                            if (v > cv1[s]) {
                                cv3[s] = fmaxf(cv3[s], cv2[s]);
                                cv2[s] = cv1[s]; ck2[s] = ck1[s];
                                cv1[s] = v;      ck1[s] = kk;
                            } else if (v > cv2[s]) {
                                cv3[s] = fmaxf(cv3[s], cv2[s]);
                                cv2[s] = v;      ck2[s] = kk;
                            } else {
                                cv3[s] = fmaxf(cv3[s], v);
                            }
                        }
                    }
                }
            }
        }
        __syncthreads();
    }

    // ---- merge: 8 writers x 3 entries per row (B buffers dead) ----
    float2* cand = (float2*)(smem + CAND_OFF);
    int* ovf_list = (int*)(smem + OVF_LIST_OFF);
    int* ovf_cnt  = (int*)(smem + OVF_CNT_OFF);
    int* sel      = (int*)(smem + SEL_OFF);
    const int wr = warp_n * 4 + t;   // 8 writers per row
    #pragma unroll
    for (int mi = 0; mi < 4; mi++) {
        #pragma unroll
        for (int h = 0; h < 2; h++) {
            const int s = mi * 2 + h;
            int row = warp_m * 64 + mi * 16 + h * 8 + g;
            float2* p = cand + ((size_t)row * 8 + wr) * 3;
            p[0] = make_float2(cv1[s], __int_as_float(ck1[s]));
            p[1] = make_float2(cv2[s], __int_as_float(ck2[s]));
            p[2] = make_float2(cv3[s], __int_as_float(-1));
        }
    }
    if (tid == 0) *ovf_cnt = 0;
    __syncthreads();

    // ---- per-row selection (one thread per row; exact recheck of survivors) ----
    {
        const int row = tid;
        const float2* p = cand + (size_t)row * 24;
        float rowmax = -CUDART_INF_F;
        for (int e = 0; e < 24; e++) rowmax = fmaxf(rowmax, p[e].x);
        const float th = rowmax - WINDOW;
        int sk[16]; int ns = 0; bool ovf = false;
        for (int e = 0; e < 24; e++) {
            if (p[e].x >= th) {
                int k = __float_as_int(p[e].y);
                if (k < 0) ovf = true;
                else if (ns < 16) sk[ns++] = k;
                else ovf = true;
            }
        }
        if (ovf) {
            int pos = atomicAdd(ovf_cnt, 1);
            ovf_list[pos] = row;
        } else {
            const int grow = rBase + row;
            int result = sk[0];
            if (ns > 1) {
                const float arow = g_a[grow];
                const float* xr = X + (size_t)grow * DIM;
                float best = CUDART_INF_F; int bestk = 0x7fffffff;
                for (int i = 0; i < ns; i++) {
                    int k = sk[i];
                    const float* wrp = W + (size_t)k * DIM;
                    float dot = 0.f;
                    #pragma unroll 8
                    for (int d = 0; d < DIM; d++) dot = fmaf(xr[d], wrp[d], dot);
                    float dist = fmaf(-2.f, dot, arow + g_c[k]);
                    if (dist < best || (dist == best && k < bestk)) { best = dist; bestk = k; }
                }
                result = bestk;
            }
            sel[row] = result;
        }
    }
    __syncthreads();

    // ---- overflow rows (expected ~0): full exact recheck, one warp per row ----
    int cnt = *ovf_cnt;
    for (int oi = wid; oi < cnt; oi += 4) {
        int row = ovf_list[oi];
        int grow = rBase + row;
        const float* xr = X + (size_t)grow * DIM;
        float arow = g_a[grow];
        float best = CUDART_INF_F; int bestk = 0x7fffffff;
        for (int kb = lane * 4; kb < KCODES; kb += 128) {
            const float* w0 = W + (size_t)(kb + 0) * DIM;
            const float* w1 = W + (size_t)(kb + 1) * DIM;
            const float* w2 = W + (size_t)(kb + 2) * DIM;
            const float* w3 = W + (size_t)(kb + 3) * DIM;
            float d0 = 0.f, d1 = 0.f, d2 = 0.f, d3 = 0.f;
            for (int d = 0; d < DIM; d++) {
                float xv = xr[d];
                d0 = fmaf(xv, w0[d], d0); d1 = fmaf(xv, w1[d], d1);
                d2 = fmaf(xv, w2[d], d2); d3 = fmaf(xv, w3[d], d3);
            }
            float dd[4];
            dd[0] = fmaf(-2.f, d0, arow + g_c[kb + 0]);
            dd[1] = fmaf(-2.f, d1, arow + g_c[kb + 1]);
            dd[2] = fmaf(-2.f, d2, arow + g_c[kb + 2]);
            dd[3] = fmaf(-2.f, d3, arow + g_c[kb + 3]);
            #pragma unroll
            for (int c = 0; c < 4; c++)
                if (dd[c] < best || (dd[c] == best && (kb + c) < bestk)) { best = dd[c]; bestk = kb + c; }
        }
        #pragma unroll
        for (int off = 16; off; off >>= 1) {
            float ob = __shfl_xor_sync(0xffffffffu, best, off);
            int   ok = __shfl_xor_sync(0xffffffffu, bestk, off);
            if (ob < best || (ob == best && ok < bestk)) { best = ob; bestk = ok; }
        }
        if (lane == 0) sel[row] = bestk;
    }
    __syncthreads();

    // ---- fused gather: each warp writes 32 rows ----
    for (int r = wid * 32; r < wid * 32 + 32; r++) {
        int k = sel[r];
        int grow = rBase + r;
        const float4* src = (const float4*)(W + (size_t)k * DIM);
        float4* dst = (float4*)(out + (size_t)grow * DIM);
        dst[lane]      = src[lane];
        dst[lane + 32] = src[lane + 32];
        if (out_idx != nullptr && lane == 0) out_idx[grow] = (float)k;
    }
}

// ---------------- launcher ----------------
extern "C" void kernel_launch(void* const* d_in, const int* in_sizes, int n_in,
                              void* d_out, int out_size) {
    const float* X = (const float*)d_in[0];
    const float* W = (const float*)d_in[1];
    if (n_in >= 2 && in_sizes[0] == KCODES * DIM && in_sizes[1] == NROWS * DIM) {
        W = (const float*)d_in[0];
        X = (const float*)d_in[1];
    }
    float* out = (float*)d_out;

    float* pa = nullptr; float* pc = nullptr;
    __half* pxh = nullptr; __half* pwh = nullptr;
    cudaGetSymbolAddress((void**)&pa, g_a);
    cudaGetSymbolAddress((void**)&pc, g_c);
    cudaGetSymbolAddress((void**)&pxh, g_xh);
    cudaGetSymbolAddress((void**)&pwh, g_wh);

    cudaFuncSetAttribute(vq_screen, cudaFuncAttributeMaxDynamicSharedMemorySize, SMEM_TOTAL);

    float* out_idx = (out_size >= NROWS * DIM + NROWS) ? (out + (size_t)NROWS * DIM) : nullptr;

    vq_prep_x<<<NROWS / 8, 256>>>(X, pa, pxh);
    vq_prep_w<<<KCODES / 8, 256>>>(W, pc, pwh);
    vq_screen<<<NROWS / BM, 128, SMEM_TOTAL>>>(X, W, pxh, pwh, out, out_idx);
}

// round 15
// speedup vs baseline: 4.2822x; 4.2822x over previous
#include <cuda_runtime.h>
#include <cuda_fp16.h>
#include <math_constants.h>
#include <stdint.h>

#define NROWS  32768
#define DIM    256
#define KCODES 8192

#define BM 128
#define BN 128
#define NTILES (KCODES / BN)   // 64
#define WINDOW 0.75f           // scaled-dot domain (dot * 4096)

#define ASTRIDE 528            // 256 f16 = 512B + 16B pad (conflict-free ldmatrix)
#define A_OFF 0
#define A_SZ  (BM * ASTRIDE)               // 67584
#define B_OFF A_SZ
#define B_SZ  (BN * ASTRIDE)               // 67584
#define SMEM_TOTAL (A_SZ + 2 * B_SZ)       // 202752

// candidate-merge area reuses the (dead) B-buffer region after the main loop
#define CAND_OFF     B_OFF                  // 128 rows * 16 writers * 4 ents * 8B = 64KB
#define OVF_LIST_OFF (B_OFF + 65536)
#define OVF_CNT_OFF  (OVF_LIST_OFF + 128 * 4)

__device__ float  g_a[NROWS];
__device__ float  g_c[KCODES];
__device__ int    g_idx[NROWS];
__device__ __align__(16) __half g_xh[NROWS * DIM];
__device__ __align__(16) __half g_wh[KCODES * DIM];   // W * 4096

// ---------------- asm helpers (sm_103-base-target legal) ----------------
__device__ __forceinline__ uint32_t smem_u32(const void* p) {
    uint32_t a;
    asm("{ .reg .u64 t; cvta.to.shared.u64 t, %1; cvt.u32.u64 %0, t; }" : "=r"(a) : "l"(p));
    return a;
}
__device__ __forceinline__ void cp16(uint32_t s, const void* g) {
    asm volatile("cp.async.cg.shared.global [%0], [%1], 16;" :: "r"(s), "l"(g));
}
#define CP_COMMIT() asm volatile("cp.async.commit_group;" ::: "memory")
#define CP_WAIT0()  asm volatile("cp.async.wait_group 0;" ::: "memory")

__device__ __forceinline__ void ldsm4(uint32_t addr, uint32_t& r0, uint32_t& r1,
                                      uint32_t& r2, uint32_t& r3) {
    asm volatile("ldmatrix.sync.aligned.m8n8.x4.shared.b16 {%0,%1,%2,%3}, [%4];"
                 : "=r"(r0), "=r"(r1), "=r"(r2), "=r"(r3) : "r"(addr));
}
__device__ __forceinline__ void mma16816(float* c, const uint32_t* a, const uint32_t* b) {
    asm volatile(
        "mma.sync.aligned.m16n8k16.row.col.f32.f16.f16.f32 "
        "{%0,%1,%2,%3}, {%4,%5,%6,%7}, {%8,%9}, {%0,%1,%2,%3};"
        : "+f"(c[0]), "+f"(c[1]), "+f"(c[2]), "+f"(c[3])
        : "r"(a[0]), "r"(a[1]), "r"(a[2]), "r"(a[3]), "r"(b[0]), "r"(b[1]));
}

// ---------------- prep kernels ----------------
__global__ void vq_prep_x(const float* __restrict__ x, float* __restrict__ a,
                          __half* __restrict__ xh) {
    int warp = (blockIdx.x * blockDim.x + threadIdx.x) >> 5;
    int lane = threadIdx.x & 31;
    if (warp >= NROWS) return;
    const float4* r4 = (const float4*)(x + (size_t)warp * DIM);
    float4 v0 = r4[lane * 2 + 0], v1 = r4[lane * 2 + 1];
    float s = 0.f;
    s = fmaf(v0.x, v0.x, s); s = fmaf(v0.y, v0.y, s); s = fmaf(v0.z, v0.z, s); s = fmaf(v0.w, v0.w, s);
    s = fmaf(v1.x, v1.x, s); s = fmaf(v1.y, v1.y, s); s = fmaf(v1.z, v1.z, s); s = fmaf(v1.w, v1.w, s);
    #pragma unroll
    for (int o = 16; o; o >>= 1) s += __shfl_xor_sync(0xffffffffu, s, o);
    if (lane == 0) a[warp] = s;
    __half2 h0 = __floats2half2_rn(v0.x, v0.y), h1 = __floats2half2_rn(v0.z, v0.w);
    __half2 h2 = __floats2half2_rn(v1.x, v1.y), h3 = __floats2half2_rn(v1.z, v1.w);
    uint4 u;
    u.x = *(unsigned*)&h0; u.y = *(unsigned*)&h1; u.z = *(unsigned*)&h2; u.w = *(unsigned*)&h3;
    ((uint4*)(xh + (size_t)warp * DIM))[lane] = u;
}
__global__ void vq_prep_w(const float* __restrict__ w, float* __restrict__ c,
                          __half* __restrict__ wh) {
    int warp = (blockIdx.x * blockDim.x + threadIdx.x) >> 5;
    int lane = threadIdx.x & 31;
    if (warp >= KCODES) return;
    const float4* r4 = (const float4*)(w + (size_t)warp * DIM);
    float4 v0 = r4[lane * 2 + 0], v1 = r4[lane * 2 + 1];
    float s = 0.f;
    s = fmaf(v0.x, v0.x, s); s = fmaf(v0.y, v0.y, s); s = fmaf(v0.z, v0.z, s); s = fmaf(v0.w, v0.w, s);
    s = fmaf(v1.x, v1.x, s); s = fmaf(v1.y, v1.y, s); s = fmaf(v1.z, v1.z, s); s = fmaf(v1.w, v1.w, s);
    #pragma unroll
    for (int o = 16; o; o >>= 1) s += __shfl_xor_sync(0xffffffffu, s, o);
    if (lane == 0) c[warp] = s;
    const float SC = 4096.0f;
    __half2 h0 = __floats2half2_rn(v0.x * SC, v0.y * SC), h1 = __floats2half2_rn(v0.z * SC, v0.w * SC);
    __half2 h2 = __floats2half2_rn(v1.x * SC, v1.y * SC), h3 = __floats2half2_rn(v1.z * SC, v1.w * SC);
    uint4 u;
    u.x = *(unsigned*)&h0; u.y = *(unsigned*)&h1; u.z = *(unsigned*)&h2; u.w = *(unsigned*)&h3;
    ((uint4*)(wh + (size_t)warp * DIM))[lane] = u;
}

// ---------------- screen kernel (HMMA) ----------------
__global__ __launch_bounds__(256, 1)
void vq_screen(const float* __restrict__ X, const float* __restrict__ W,
               const __half* __restrict__ Xh, const __half* __restrict__ Wh) {
    extern __shared__ char smem[];
    const uint32_t sb = smem_u32(smem);
    const int tid = threadIdx.x;
    const int wid = tid >> 5, lane = tid & 31;
    const int warp_m = wid >> 2, warp_n = wid & 3;
    const int g = lane >> 2, t = lane & 3;
    const int rBase = blockIdx.x * BM;

    // ---- prologue: A tile + B tile 0 via cp.async ----
    #pragma unroll
    for (int i = 0; i < 16; i++) {
        int idx = tid + i * 256;
        int row = idx >> 5, c = idx & 31;
        cp16(sb + A_OFF + row * ASTRIDE + c * 16,
             Xh + (size_t)(rBase + row) * DIM + c * 8);
    }
    #pragma unroll
    for (int i = 0; i < 16; i++) {
        int idx = tid + i * 256;
        int row = idx >> 5, c = idx & 31;
        cp16(sb + B_OFF + row * ASTRIDE + c * 16,
             Wh + (size_t)row * DIM + c * 8);
    }
    CP_COMMIT();

    // per-(lane,slot) running top-3 (+v4 overflow value); slot s = mi*2+h
    float cv1[8], cv2[8], cv3[8], cv4[8];
    int   ck1[8], ck2[8], ck3[8];
    #pragma unroll
    for (int s = 0; s < 8; s++) {
        cv1[s] = cv2[s] = cv3[s] = cv4[s] = -CUDART_INF_F;
        ck1[s] = ck2[s] = ck3[s] = 0;
    }

    // ldmatrix base addresses
    const uint32_t a_base = sb + A_OFF +
        (uint32_t)(warp_m * 64 + (lane & 15)) * ASTRIDE + (uint32_t)(lane >> 4) * 16;
    const uint32_t b_row_off =
        (uint32_t)(warp_n * 32 + (lane & 7) + (lane >> 4) * 8) * ASTRIDE +
        (uint32_t)((lane >> 3) & 1) * 16;

    for (int nt = 0; nt < NTILES; nt++) {
        CP_WAIT0();
        __syncthreads();
        if (nt + 1 < NTILES) {
            int buf = (nt + 1) & 1;
            #pragma unroll
            for (int i = 0; i < 16; i++) {
                int idx = tid + i * 256;
                int row = idx >> 5, c = idx & 31;
                cp16(sb + B_OFF + buf * B_SZ + row * ASTRIDE + c * 16,
                     Wh + (size_t)((nt + 1) * BN + row) * DIM + c * 8);
            }
            CP_COMMIT();
        }

        // ---- GEMM: 64x32 warp tile over K=256 ----
        float acc[4][4][4];
        #pragma unroll
        for (int mi = 0; mi < 4; mi++)
            #pragma unroll
            for (int ni = 0; ni < 4; ni++)
                #pragma unroll
                for (int c = 0; c < 4; c++) acc[mi][ni][c] = 0.f;

        const uint32_t b_base = sb + B_OFF + (uint32_t)(nt & 1) * B_SZ + b_row_off;
        #pragma unroll 4
        for (int ks = 0; ks < 16; ks++) {
            uint32_t af[4][4], bf[4][2];
            #pragma unroll
            for (int mi = 0; mi < 4; mi++)
                ldsm4(a_base + (uint32_t)mi * 16 * ASTRIDE + (uint32_t)ks * 32,
                      af[mi][0], af[mi][1], af[mi][2], af[mi][3]);
            ldsm4(b_base + (uint32_t)ks * 32, bf[0][0], bf[0][1], bf[1][0], bf[1][1]);
            ldsm4(b_base + 16u * ASTRIDE + (uint32_t)ks * 32,
                  bf[2][0], bf[2][1], bf[3][0], bf[3][1]);
            #pragma unroll
            for (int mi = 0; mi < 4; mi++)
                #pragma unroll
                for (int ni = 0; ni < 4; ni++)
                    mma16816(acc[mi][ni], af[mi], bf[ni]);
        }

        // ---- epilogue: per-slot top-3 update ----
        #pragma unroll
        for (int mi = 0; mi < 4; mi++) {
            #pragma unroll
            for (int h = 0; h < 2; h++) {
                const int s = mi * 2 + h;
                float tm = fmaxf(fmaxf(fmaxf(acc[mi][0][2*h], acc[mi][0][2*h+1]),
                                       fmaxf(acc[mi][1][2*h], acc[mi][1][2*h+1])),
                                 fmaxf(fmaxf(acc[mi][2][2*h], acc[mi][2][2*h+1]),
                                       fmaxf(acc[mi][3][2*h], acc[mi][3][2*h+1])));
                if (tm <= cv3[s]) {
                    cv4[s] = fmaxf(cv4[s], tm);   // nothing enters top-3
                } else {
                    #pragma unroll
                    for (int ni = 0; ni < 4; ni++) {
                        #pragma unroll
                        for (int c = 0; c < 2; c++) {
                            float v = acc[mi][ni][2 * h + c];
                            int kk = nt * BN + warp_n * 32 + ni * 8 + 2 * t + c;
                            if (v > cv1[s]) {
                                cv4[s] = fmaxf(cv4[s], cv3[s]);
                                cv3[s] = cv2[s]; ck3[s] = ck2[s];
                                cv2[s] = cv1[s]; ck2[s] = ck1[s];
                                cv1[s] = v;      ck1[s] = kk;
                            } else if (v > cv2[s]) {
                                cv4[s] = fmaxf(cv4[s], cv3[s]);
                                cv3[s] = cv2[s]; ck3[s] = ck2[s];
                                cv2[s] = v;      ck2[s] = kk;
                            } else if (v > cv3[s]) {
                                cv4[s] = fmaxf(cv4[s], cv3[s]);
                                cv3[s] = v;      ck3[s] = kk;
                            } else {
                                cv4[s] = fmaxf(cv4[s], v);
                            }
                        }
                    }
                }
            }
        }
        __syncthreads();
    }

    // ---- merge: write candidates to smem (B buffers are dead now) ----
    float2* cand = (float2*)(smem + CAND_OFF);
    int* ovf_list = (int*)(smem + OVF_LIST_OFF);
    int* ovf_cnt  = (int*)(smem + OVF_CNT_OFF);
    const int wr = warp_n * 4 + t;
    #pragma unroll
    for (int mi = 0; mi < 4; mi++) {
        #pragma unroll
        for (int h = 0; h < 2; h++) {
            const int s = mi * 2 + h;
            int row = warp_m * 64 + mi * 16 + h * 8 + g;
            float2* p = cand + ((size_t)row * 16 + wr) * 4;
            p[0] = make_float2(cv1[s], __int_as_float(ck1[s]));
            p[1] = make_float2(cv2[s], __int_as_float(ck2[s]));
            p[2] = make_float2(cv3[s], __int_as_float(ck3[s]));
            p[3] = make_float2(cv4[s], __int_as_float(-1));
        }
    }
    if (tid == 0) *ovf_cnt = 0;
    __syncthreads();

    // ---- per-row selection (one thread per row) ----
    if (tid < BM) {
        const int row = tid;
        const float2* p = cand + (size_t)row * 64;
        float rowmax = -CUDART_INF_F;
        for (int e = 0; e < 64; e++) rowmax = fmaxf(rowmax, p[e].x);
        const float th = rowmax - WINDOW;
        int sk[16]; int ns = 0; bool ovf = false;
        for (int e = 0; e < 64; e++) {
            float v = p[e].x;
            if (v >= th) {
                int k = __float_as_int(p[e].y);
                if (k < 0) ovf = true;
                else if (ns < 16) sk[ns++] = k;
                else ovf = true;
            }
        }
        if (ovf) {
            int pos = atomicAdd(ovf_cnt, 1);
            ovf_list[pos] = row;
        } else {
            const int grow = rBase + row;
            int result = sk[0];
            if (ns > 1) {
                const float arow = g_a[grow];
                const float* xr = X + (size_t)grow * DIM;
                float best = CUDART_INF_F; int bestk = 0x7fffffff;
                for (int i = 0; i < ns; i += 2) {
                    int k0 = sk[i];
                    int k1 = (i + 1 < ns) ? sk[i + 1] : sk[i];
                    const float* w0 = W + (size_t)k0 * DIM;
                    const float* w1 = W + (size_t)k1 * DIM;
                    float d0 = 0.f, d1 = 0.f;
                    for (int d = 0; d < DIM; d++) {
                        float xv = xr[d];
                        d0 = fmaf(xv, w0[d], d0);
                        d1 = fmaf(xv, w1[d], d1);
                    }
                    float dist0 = fmaf(-2.f, d0, arow + g_c[k0]);
                    float dist1 = fmaf(-2.f, d1, arow + g_c[k1]);
                    if (dist0 < best || (dist0 == best && k0 < bestk)) { best = dist0; bestk = k0; }
                    if (i + 1 < ns && (dist1 < best || (dist1 == best && k1 < bestk))) { best = dist1; bestk = k1; }
                }
                result = bestk;
            }
            g_idx[grow] = result;
        }
    }
    __syncthreads();

    // ---- overflow rows (expected ~0): full exact recheck, one warp per row ----
    int cnt = *ovf_cnt;
    for (int oi = wid; oi < cnt; oi += 8) {
        int row = ovf_list[oi];
        int grow = rBase + row;
        const float* xr = X + (size_t)grow * DIM;
        float arow = g_a[grow];
        float best = CUDART_INF_F; int bestk = 0x7fffffff;
        for (int kb = lane * 4; kb < KCODES; kb += 128) {
            const float* w0 = W + (size_t)(kb + 0) * DIM;
            const float* w1 = W + (size_t)(kb + 1) * DIM;
            const float* w2 = W + (size_t)(kb + 2) * DIM;
            const float* w3 = W + (size_t)(kb + 3) * DIM;
            float d0 = 0.f, d1 = 0.f, d2 = 0.f, d3 = 0.f;
            for (int d = 0; d < DIM; d++) {
                float xv = xr[d];
                d0 = fmaf(xv, w0[d], d0); d1 = fmaf(xv, w1[d], d1);
                d2 = fmaf(xv, w2[d], d2); d3 = fmaf(xv, w3[d], d3);
            }
            float dd[4];
            dd[0] = fmaf(-2.f, d0, arow + g_c[kb + 0]);
            dd[1] = fmaf(-2.f, d1, arow + g_c[kb + 1]);
            dd[2] = fmaf(-2.f, d2, arow + g_c[kb + 2]);
            dd[3] = fmaf(-2.f, d3, arow + g_c[kb + 3]);
            #pragma unroll
            for (int c = 0; c < 4; c++)
                if (dd[c] < best || (dd[c] == best && (kb + c) < bestk)) { best = dd[c]; bestk = kb + c; }
        }
        #pragma unroll
        for (int off = 16; off; off >>= 1) {
            float ob = __shfl_xor_sync(0xffffffffu, best, off);
            int   ok = __shfl_xor_sync(0xffffffffu, bestk, off);
            if (ob < best || (ob == best && ok < bestk)) { best = ob; bestk = ok; }
        }
        if (lane == 0) g_idx[grow] = bestk;
    }
}

// ---------------- gather ----------------
__global__ void vq_gather_kernel(const float* __restrict__ W,
                                 float* __restrict__ out,
                                 float* __restrict__ out_idx) {
    int warp = (blockIdx.x * blockDim.x + threadIdx.x) >> 5;
    int lane = threadIdx.x & 31;
    if (warp >= NROWS) return;
    int k = g_idx[warp];
    const float4* src = (const float4*)(W + (size_t)k * DIM);
    float4* dst = (float4*)(out + (size_t)warp * DIM);
    dst[lane]      = src[lane];
    dst[lane + 32] = src[lane + 32];
    if (out_idx != nullptr && lane == 0) out_idx[warp] = (float)k;
}

// ---------------- launcher ----------------
extern "C" void kernel_launch(void* const* d_in, const int* in_sizes, int n_in,
                              void* d_out, int out_size) {
    const float* X = (const float*)d_in[0];
    const float* W = (const float*)d_in[1];
    if (n_in >= 2 && in_sizes[0] == KCODES * DIM && in_sizes[1] == NROWS * DIM) {
        W = (const float*)d_in[0];
        X = (const float*)d_in[1];
    }
    float* out = (float*)d_out;

    float* pa = nullptr; float* pc = nullptr;
    __half* pxh = nullptr; __half* pwh = nullptr;
    cudaGetSymbolAddress((void**)&pa, g_a);
    cudaGetSymbolAddress((void**)&pc, g_c);
    cudaGetSymbolAddress((void**)&pxh, g_xh);
    cudaGetSymbolAddress((void**)&pwh, g_wh);

    cudaFuncSetAttribute(vq_screen, cudaFuncAttributeMaxDynamicSharedMemorySize, SMEM_TOTAL);

    vq_prep_x<<<NROWS / 8, 256>>>(X, pa, pxh);
    vq_prep_w<<<KCODES / 8, 256>>>(W, pc, pwh);
    vq_screen<<<NROWS / BM, 256, SMEM_TOTAL>>>(X, W, pxh, pwh);

    float* out_idx = (out_size >= NROWS * DIM + NROWS) ? (out + (size_t)NROWS * DIM) : nullptr;
    vq_gather_kernel<<<NROWS / 8, 256>>>(W, out, out_idx);
}